// round 12
// baseline (speedup 1.0000x reference)
#include <cuda_runtime.h>
#include <cuda_bf16.h>
#include <math.h>
#include <stdint.h>

// Problem constants
#define BB   4
#define TT   1024
#define HIDN 1024
#define NH   8
#define CDIM 3072   // 2*H*DK + H*DV
#define NBIG 4096   // merged N: qkv (3072) + z (1024)
#define KPHY 2048   // physical row: [hi(1024) | lo(1024)]
// logical K = 3072 via section remap: A sec{0,2}->hi sec1->lo ; B sec{0,1}->hi sec2->lo

// GEMM pipeline geometry
#define STAGES      3
#define STAGE_BYTES 36864          // 2 operands * 128 rows * 144B
#define GSMEM       (STAGES * STAGE_BYTES)   // 110592 dynamic

// ---------------------------------------------------------------------------
// Scratch (device globals; allocation is forbidden)
// ---------------------------------------------------------------------------
__device__ float g_mixed[(size_t)BB * TT * CDIM];
__device__ float g_qkvc [(size_t)BB * TT * CDIM];
__device__ float g_z    [(size_t)BB * TT * HIDN];
__device__ float g_opre [(size_t)BB * TT * HIDN];
__device__ float g_alpha[(size_t)BB * NH * TT];
__device__ float g_beta [(size_t)BB * NH * TT];

__device__ __nv_bfloat16 g_A3hs [(size_t)BB * TT * KPHY];   // hidden_states [hi|lo]
__device__ __nv_bfloat16 g_A3og [(size_t)BB * TT * KPHY];   // gated output  [hi|lo]
__device__ __nv_bfloat16 g_B3big[(size_t)NBIG * KPHY];      // [qkv_w ; z_w] [hi|lo]
__device__ __nv_bfloat16 g_B3out[(size_t)HIDN * KPHY];      // out_w         [hi|lo]

// ---------------------------------------------------------------------------
// Base-ISA helpers (sm_80+ only: harness PTX targets compute_103, no 'a').
// ---------------------------------------------------------------------------
__device__ __forceinline__ uint32_t smem_u32(const void* p) {
    return (uint32_t)__cvta_generic_to_shared(p);
}
__device__ __forceinline__ void cp_async16(uint32_t dst, const void* src) {
    asm volatile("cp.async.cg.shared.global [%0], [%1], 16;" :: "r"(dst), "l"(src) : "memory");
}
#define CP_COMMIT() asm volatile("cp.async.commit_group;" ::: "memory")
#define CP_WAIT1()  asm volatile("cp.async.wait_group 1;" ::: "memory")

__device__ __forceinline__ void ldsm_x4(uint32_t* r, uint32_t addr) {
    asm volatile("ldmatrix.sync.aligned.m8n8.x4.shared.b16 {%0,%1,%2,%3}, [%4];"
                 : "=r"(r[0]), "=r"(r[1]), "=r"(r[2]), "=r"(r[3]) : "r"(addr));
}
__device__ __forceinline__ void mma16816(float* c, const uint32_t* a, uint32_t b0, uint32_t b1) {
    asm volatile("mma.sync.aligned.m16n8k16.row.col.f32.bf16.bf16.f32 "
                 "{%0,%1,%2,%3}, {%4,%5,%6,%7}, {%8,%9}, {%0,%1,%2,%3};"
                 : "+f"(c[0]), "+f"(c[1]), "+f"(c[2]), "+f"(c[3])
                 : "r"(a[0]), "r"(a[1]), "r"(a[2]), "r"(a[3]), "r"(b0), "r"(b1));
}

// hi/lo split helpers
__device__ __forceinline__ void split_bf16(float x, __nv_bfloat16& h, __nv_bfloat16& l) {
    h = __float2bfloat16_rn(x);
    l = __float2bfloat16_rn(x - __bfloat162float(h));
}
__device__ __forceinline__ void st_bf16x4(__nv_bfloat16* p, __nv_bfloat16 a, __nv_bfloat16 b,
                                          __nv_bfloat16 c, __nv_bfloat16 d) {
    __nv_bfloat162 v0; v0.x = a; v0.y = b;
    __nv_bfloat162 v1; v1.x = c; v1.y = d;
    *(__nv_bfloat162*)(p)     = v0;
    *(__nv_bfloat162*)(p + 2) = v1;
}

// ---------------------------------------------------------------------------
// Operand conversion: fp32 -> [hi|lo] bf16 pair rows (2048 wide)
// ---------------------------------------------------------------------------
__global__ void __launch_bounds__(256) convert_hs_kernel(const float* __restrict__ hs) {
    const int row = blockIdx.x;
    const int c   = threadIdx.x * 4;
    float4 x = *(const float4*)(hs + (size_t)row * 1024 + c);
    __nv_bfloat16 h0, h1, h2, h3, l0, l1, l2, l3;
    split_bf16(x.x, h0, l0); split_bf16(x.y, h1, l1);
    split_bf16(x.z, h2, l2); split_bf16(x.w, h3, l3);
    __nv_bfloat16* dst = g_A3hs + (size_t)row * KPHY + c;
    st_bf16x4(dst,        h0, h1, h2, h3);
    st_bf16x4(dst + 1024, l0, l1, l2, l3);
}

// merged weight convert: rows [0,3072) from qkv_w, rows [3072,4096) from z_w
__global__ void __launch_bounds__(256) convert_w_big(const float* __restrict__ qkv_w,
                                                     const float* __restrict__ z_w) {
    const int row = blockIdx.x;
    const int c   = threadIdx.x * 4;
    const float* src = (row < 3072) ? (qkv_w + (size_t)row * 1024)
                                    : (z_w + (size_t)(row - 3072) * 1024);
    float4 x = *(const float4*)(src + c);
    __nv_bfloat16 h0, h1, h2, h3, l0, l1, l2, l3;
    split_bf16(x.x, h0, l0); split_bf16(x.y, h1, l1);
    split_bf16(x.z, h2, l2); split_bf16(x.w, h3, l3);
    __nv_bfloat16* dst = g_B3big + (size_t)row * KPHY + c;
    st_bf16x4(dst,        h0, h1, h2, h3);
    st_bf16x4(dst + 1024, l0, l1, l2, l3);
}

__global__ void __launch_bounds__(256) convert_w_out(const float* __restrict__ src) {
    const int row = blockIdx.x;
    const int c   = threadIdx.x * 4;
    float4 x = *(const float4*)(src + (size_t)row * 1024 + c);
    __nv_bfloat16 h0, h1, h2, h3, l0, l1, l2, l3;
    split_bf16(x.x, h0, l0); split_bf16(x.y, h1, l1);
    split_bf16(x.z, h2, l2); split_bf16(x.w, h3, l3);
    __nv_bfloat16* dst = g_B3out + (size_t)row * KPHY + c;
    st_bf16x4(dst,        h0, h1, h2, h3);
    st_bf16x4(dst + 1024, l0, l1, l2, l3);
}

// ---------------------------------------------------------------------------
// HMMA GEMM (NT): C[M,N] = A'[M,3072] * B'[N,3072]^T via section remap.
// 128x128 tile, BK=64 (48 stages), 3-stage cp.async ring (next load issued
// BEFORE compute -> ~2 stages of lead), 256 threads, warp tile 64x32.
// smem rows: 128B data + 16B pad (144B stride; ldmatrix conflict-free).
//   WHICH 0: A3hs x B3big (N=4096) -> cols<3072 g_mixed, else g_z
//   WHICH 1: A3og x B3out (N=1024) -> Cext
// ---------------------------------------------------------------------------
template <int WHICH>
__global__ void __launch_bounds__(256, 2) gemm_mma(float* __restrict__ Cext) {
    const __nv_bfloat16* A = WHICH ? g_A3og : g_A3hs;
    const __nv_bfloat16* B = WHICH ? g_B3out : g_B3big;

    extern __shared__ __align__(16) char smem[];
    const uint32_t sB = smem_u32(smem);

    const int tid  = threadIdx.x;
    const int bn   = blockIdx.x * 128;
    const int bm   = blockIdx.y * 128;
    const int warp = tid >> 5, lane = tid & 31;
    const int wm   = (warp >> 2) * 64;
    const int wn   = (warp & 3) * 32;

    float acc[4][4][4];
#pragma unroll
    for (int im = 0; im < 4; im++)
#pragma unroll
        for (int in = 0; in < 4; in++)
#pragma unroll
            for (int r = 0; r < 4; r++) acc[im][in][r] = 0.f;

    // loader: thread -> (row 0..127, half 0..1); 4 x 16B chunks per operand
    const int row  = tid >> 1;
    const int half = tid & 1;
    const __nv_bfloat16* Agr = A + (size_t)(bm + row) * KPHY + half * 32;
    const __nv_bfloat16* Bgr = B + (size_t)(bn + row) * KPHY + half * 32;
    const uint32_t dloc = row * 144 + half * 64;

    auto load_stage = [&](int s) {
        const int k0  = s * 64;
        const int sec = k0 >> 10, rem = k0 & 1023;
        const int aoff = (sec == 1) ? 1024 + rem : rem;   // A: [hi,lo,hi]
        const int boff = (sec == 2) ? 1024 + rem : rem;   // B: [hi,hi,lo]
        const uint32_t as = sB + (s % STAGES) * STAGE_BYTES + dloc;
        const uint32_t bs = as + 18432;
        const __nv_bfloat16* ag = Agr + aoff;
        const __nv_bfloat16* bg = Bgr + boff;
        cp_async16(as,      ag);
        cp_async16(as + 16, ag + 8);
        cp_async16(as + 32, ag + 16);
        cp_async16(as + 48, ag + 24);
        cp_async16(bs,      bg);
        cp_async16(bs + 16, bg + 8);
        cp_async16(bs + 32, bg + 16);
        cp_async16(bs + 48, bg + 24);
        CP_COMMIT();
    };

    load_stage(0);
    load_stage(1);

    const int NT = 48;   // 3*1024/64
    for (int s = 0; s < NT; s++) {
        CP_WAIT1();            // load s complete (s+1 may still be in flight)
        __syncthreads();
        if (s + 2 < NT) load_stage(s + 2);   // issued BEFORE compute: ~2-stage lead

        const uint32_t base = sB + (s % STAGES) * STAGE_BYTES;
        const uint32_t aF = base + (wm + (lane & 15)) * 144 + (lane >> 4) * 16;
        const uint32_t bF = base + 18432 + (wn + (lane & 15)) * 144 + (lane >> 4) * 16;

#pragma unroll
        for (int ks = 0; ks < 64; ks += 16) {
            uint32_t bfr[2][4];
            ldsm_x4(bfr[0], bF + ks * 2);
            ldsm_x4(bfr[1], bF + 16 * 144 + ks * 2);
#pragma unroll
            for (int im = 0; im < 4; im++) {
                uint32_t afr[4];
                ldsm_x4(afr, aF + im * (16 * 144) + ks * 2);
                mma16816(acc[im][0], afr, bfr[0][0], bfr[0][2]);
                mma16816(acc[im][1], afr, bfr[0][1], bfr[0][3]);
                mma16816(acc[im][2], afr, bfr[1][0], bfr[1][2]);
                mma16816(acc[im][3], afr, bfr[1][1], bfr[1][3]);
            }
        }
    }

    // epilogue: route output
    float* Cb; int stride, cb;
    if (WHICH == 1)     { Cb = Cext;    stride = 1024; cb = bn; }
    else if (bn < 3072) { Cb = g_mixed; stride = 3072; cb = bn; }
    else                { Cb = g_z;     stride = 1024; cb = bn - 3072; }

    const int er = lane >> 2;
    const int ec = (lane & 3) * 2;
#pragma unroll
    for (int im = 0; im < 4; im++) {
#pragma unroll
        for (int in = 0; in < 4; in++) {
            const int r0  = bm + wm + im * 16 + er;
            const int col = cb + wn + in * 8 + ec;
            *(float2*)&Cb[(size_t)r0 * stride + col]       = make_float2(acc[im][in][0], acc[im][in][1]);
            *(float2*)&Cb[(size_t)(r0 + 8) * stride + col] = make_float2(acc[im][in][2], acc[im][in][3]);
        }
    }
}

// ---------------------------------------------------------------------------
// b/a projections + beta / alpha (fp32: alpha feeds exp())
// ---------------------------------------------------------------------------
__global__ void __launch_bounds__(256) smallproj_kernel(const float* __restrict__ hs,
                                                        const float* __restrict__ b_w,
                                                        const float* __restrict__ a_w,
                                                        const float* __restrict__ dt_bias,
                                                        const float* __restrict__ A_log) {
    __shared__ float sh[1024];
    const int bt  = blockIdx.x;
    const int tid = threadIdx.x;
    const float* row = hs + (size_t)bt * 1024;
    *(float4*)&sh[tid * 4] = *(const float4*)(row + tid * 4);
    __syncthreads();

    const int h = tid >> 5, lane = tid & 31;
    const float* bw = b_w + h * 1024;
    const float* aw = a_w + h * 1024;
    float sb = 0.f, sa = 0.f;
#pragma unroll
    for (int i = 0; i < 8; i++) {
        int idx = lane * 4 + i * 128;
        float4 x  = *(float4*)&sh[idx];
        float4 wb = *(const float4*)(bw + idx);
        float4 wa = *(const float4*)(aw + idx);
        sb += x.x * wb.x + x.y * wb.y + x.z * wb.z + x.w * wb.w;
        sa += x.x * wa.x + x.y * wa.y + x.z * wa.z + x.w * wa.w;
    }
#pragma unroll
    for (int m = 16; m; m >>= 1) {
        sb += __shfl_xor_sync(0xffffffffu, sb, m);
        sa += __shfl_xor_sync(0xffffffffu, sa, m);
    }
    if (lane == 0) {
        float beta = 1.f / (1.f + expf(-sb));
        float x  = sa + dt_bias[h];
        float sp = (x > 20.f) ? x : log1pf(expf(x));
        float g  = -expf(A_log[h]) * sp;
        int b = bt >> 10, t = bt & 1023;
        g_alpha[((b * NH + h) << 10) + t] = expf(g);
        g_beta [((b * NH + h) << 10) + t] = beta;
    }
}

// ---------------------------------------------------------------------------
// Causal depthwise conv1d (K=4)
// ---------------------------------------------------------------------------
__global__ void __launch_bounds__(256) conv_kernel(const float* __restrict__ conv_w) {
    const int c  = blockIdx.x * 256 + threadIdx.x;
    const int t0 = blockIdx.y * 128;
    const int b  = blockIdx.z;
    float4 w4 = *(const float4*)(conv_w + c * 4);
    const float* xin  = g_mixed + (size_t)b * TT * CDIM + c;
    float*       yout = g_qkvc  + (size_t)b * TT * CDIM + c;
    float x0 = (t0 >= 3) ? xin[(size_t)(t0 - 3) * CDIM] : 0.f;
    float x1 = (t0 >= 2) ? xin[(size_t)(t0 - 2) * CDIM] : 0.f;
    float x2 = (t0 >= 1) ? xin[(size_t)(t0 - 1) * CDIM] : 0.f;
#pragma unroll 4
    for (int t = t0; t < t0 + 128; t++) {
        float x3 = xin[(size_t)t * CDIM];
        yout[(size_t)t * CDIM] = w4.x * x0 + w4.y * x1 + w4.z * x2 + w4.w * x3;
        x0 = x1; x1 = x2; x2 = x3;
    }
}

// ---------------------------------------------------------------------------
// Gated delta-rule scan (R8 v2 body — empirically best).
// grid = (4 dv-chunks, H, B) = 128 CTAs, 256 threads.
// ---------------------------------------------------------------------------
__global__ void __launch_bounds__(256) scan_kernel() {
    __shared__ float sk[16][160];
    __shared__ float sq[16][160];
    __shared__ float sv[16][32];
    __shared__ float so[16][32];
    __shared__ float sal[16];
    __shared__ float sbe[16];

    const int tid   = threadIdx.x;
    const int chunk = blockIdx.x;
    const int h     = blockIdx.y;
    const int b     = blockIdx.z;

    const int lane  = tid & 31;
    const int w     = tid >> 5;
    const int split = lane & 7;
    const int col   = w * 4 + (lane >> 3);
    const int kbp   = split * 20;

    const float* qbase = g_qkvc + (size_t)b * TT * CDIM + h * 128;
    const float* abase = g_alpha + ((size_t)(b * NH + h) << 10);
    const float* bbase = g_beta  + ((size_t)(b * NH + h) << 10);

    float S[16];
#pragma unroll
    for (int j = 0; j < 16; j++) S[j] = 0.f;

    const int ltt  = tid >> 4;
    const int lseg = tid & 15;
    const int cc0  = lseg * 8;
    const int cc1  = cc0 + 4;
    const int d0   = cc0 + ((cc0 >> 4) << 2);
    const int d1   = cc1 + ((cc1 >> 4) << 2);

    float4 pq0, pq1, pk0, pk1, pv;
    float pal = 0.f, pbe = 0.f;
    {
        const float* row = qbase + (size_t)ltt * CDIM;
        pq0 = *(const float4*)(row + cc0);
        pq1 = *(const float4*)(row + cc1);
        pk0 = *(const float4*)(row + 1024 + cc0);
        pk1 = *(const float4*)(row + 1024 + cc1);
        if (lseg < 8) pv = *(const float4*)(row + 2048 + chunk * 32 + lseg * 4);
        if (tid < 16) { pal = abase[tid]; pbe = bbase[tid]; }
    }

    for (int t0 = 0; t0 < TT; t0 += 16) {
        __syncthreads();
        if (t0 > 0) {
            for (int idx = tid; idx < 512; idx += 256) {
                int tt = idx >> 5, dd = idx & 31;
                g_opre[(((size_t)(b * TT + (t0 - 16) + tt)) * NH + h) * 128 + chunk * 32 + dd] = so[tt][dd];
            }
        }
        *(float4*)&sq[ltt][d0] = pq0;
        *(float4*)&sq[ltt][d1] = pq1;
        *(float4*)&sk[ltt][d0] = pk0;
        *(float4*)&sk[ltt][d1] = pk1;
        if (lseg < 8) *(float4*)&sv[ltt][lseg * 4] = pv;
        if (tid < 16) { sal[tid] = pal; sbe[tid] = pbe; }
        __syncthreads();

        if (t0 + 16 < TT) {
            const float* row = qbase + (size_t)(t0 + 16 + ltt) * CDIM;
            pq0 = *(const float4*)(row + cc0);
            pq1 = *(const float4*)(row + cc1);
            pk0 = *(const float4*)(row + 1024 + cc0);
            pk1 = *(const float4*)(row + 1024 + cc1);
            if (lseg < 8) pv = *(const float4*)(row + 2048 + chunk * 32 + lseg * 4);
            if (tid < 16) { pal = abase[t0 + 16 + tid]; pbe = bbase[t0 + 16 + tid]; }
        }

#pragma unroll 2
        for (int tt = 0; tt < 16; tt++) {
            const float alpha = sal[tt];
            const float beta  = sbe[tt];

            float kr[16];
#pragma unroll
            for (int uu = 0; uu < 4; uu++)
                *(float4*)&kr[uu * 4] = *(float4*)&sk[tt][kbp + uu * 4];

            float kva = 0.f, kvb = 0.f, kvc = 0.f, kvd = 0.f;
#pragma unroll
            for (int j = 0; j < 16; j += 4) {
                S[j]     *= alpha; kva = fmaf(kr[j],     S[j],     kva);
                S[j + 1] *= alpha; kvb = fmaf(kr[j + 1], S[j + 1], kvb);
                S[j + 2] *= alpha; kvc = fmaf(kr[j + 2], S[j + 2], kvc);
                S[j + 3] *= alpha; kvd = fmaf(kr[j + 3], S[j + 3], kvd);
            }
            float kv = (kva + kvb) + (kvc + kvd);
            kv += __shfl_xor_sync(0xffffffffu, kv, 1);
            kv += __shfl_xor_sync(0xffffffffu, kv, 2);
            kv += __shfl_xor_sync(0xffffffffu, kv, 4);

            const float wv = (sv[tt][col] - kv) * beta;

            float qr[16];
#pragma unroll
            for (int uu = 0; uu < 4; uu++)
                *(float4*)&qr[uu * 4] = *(float4*)&sq[tt][kbp + uu * 4];

            float oa = 0.f, ob = 0.f, oc = 0.f, od = 0.f;
#pragma unroll
            for (int j = 0; j < 16; j += 4) {
                S[j]     = fmaf(kr[j],     wv, S[j]);     oa = fmaf(qr[j],     S[j],     oa);
                S[j + 1] = fmaf(kr[j + 1], wv, S[j + 1]); ob = fmaf(qr[j + 1], S[j + 1], ob);
                S[j + 2] = fmaf(kr[j + 2], wv, S[j + 2]); oc = fmaf(qr[j + 2], S[j + 2], oc);
                S[j + 3] = fmaf(kr[j + 3], wv, S[j + 3]); od = fmaf(qr[j + 3], S[j + 3], od);
            }
            float o = (oa + ob) + (oc + od);
            o += __shfl_xor_sync(0xffffffffu, o, 1);
            o += __shfl_xor_sync(0xffffffffu, o, 2);
            o += __shfl_xor_sync(0xffffffffu, o, 4);
            if (split == 0) so[tt][col] = o;
        }
    }

    __syncthreads();
    for (int idx = tid; idx < 512; idx += 256) {
        int tt = idx >> 5, dd = idx & 31;
        g_opre[(((size_t)(b * TT + (TT - 16) + tt)) * NH + h) * 128 + chunk * 32 + dd] = so[tt][dd];
    }
}

// ---------------------------------------------------------------------------
// Gated RMSNorm fused with [hi|lo] bf16 emission for the out GEMM A operand
// ---------------------------------------------------------------------------
__global__ void __launch_bounds__(256) normgate_kernel(const float* __restrict__ norm_w) {
    const int bt   = blockIdx.x;
    const int h    = threadIdx.x >> 5;
    const int lane = threadIdx.x & 31;

    const size_t obase = ((size_t)bt * NH + h) * 128 + lane * 4;
    float4 o4 = *(const float4*)(g_opre + obase);
    float ss = o4.x * o4.x + o4.y * o4.y + o4.z * o4.z + o4.w * o4.w;
#pragma unroll
    for (int m = 16; m; m >>= 1) ss += __shfl_xor_sync(0xffffffffu, ss, m);
    const float scale = rsqrtf(ss * (1.f / 128.f) + 1e-6f);

    const size_t zbase = (size_t)bt * 1024 + h * 128 + lane * 4;
    float4 z4 = *(const float4*)(g_z + zbase);
    float4 nw = *(const float4*)(norm_w + lane * 4);
    float rx = o4.x * scale * nw.x * (z4.x / (1.f + expf(-z4.x)));
    float ry = o4.y * scale * nw.y * (z4.y / (1.f + expf(-z4.y)));
    float rz = o4.z * scale * nw.z * (z4.z / (1.f + expf(-z4.z)));
    float rw = o4.w * scale * nw.w * (z4.w / (1.f + expf(-z4.w)));

    __nv_bfloat16 h0, h1, h2, h3, l0, l1, l2, l3;
    split_bf16(rx, h0, l0); split_bf16(ry, h1, l1);
    split_bf16(rz, h2, l2); split_bf16(rw, h3, l3);
    __nv_bfloat16* dst = g_A3og + (size_t)bt * KPHY + h * 128 + lane * 4;
    st_bf16x4(dst,        h0, h1, h2, h3);
    st_bf16x4(dst + 1024, l0, l1, l2, l3);
}

// ---------------------------------------------------------------------------
// kernel_launch  (gemm_mma<0> kept at launch index 3 = the profiled slot)
// ---------------------------------------------------------------------------
extern "C" void kernel_launch(void* const* d_in, const int* in_sizes, int n_in,
                              void* d_out, int out_size) {
    const float* hs      = (const float*)d_in[0];
    const float* qkv_w   = (const float*)d_in[1];
    const float* z_w     = (const float*)d_in[2];
    const float* b_w     = (const float*)d_in[3];
    const float* a_w     = (const float*)d_in[4];
    const float* conv_w  = (const float*)d_in[5];
    const float* dt_bias = (const float*)d_in[6];
    const float* A_log   = (const float*)d_in[7];
    const float* norm_w  = (const float*)d_in[8];
    const float* out_w   = (const float*)d_in[9];
    float* out = (float*)d_out;

    // idempotent attribute set (host-side, not a stream op; capture-safe)
    cudaFuncSetAttribute(gemm_mma<0>, cudaFuncAttributeMaxDynamicSharedMemorySize, GSMEM);
    cudaFuncSetAttribute(gemm_mma<1>, cudaFuncAttributeMaxDynamicSharedMemorySize, GSMEM);

    convert_hs_kernel<<<BB * TT, 256>>>(hs);                                    // 0
    convert_w_big<<<NBIG, 256>>>(qkv_w, z_w);                                   // 1
    convert_w_out<<<HIDN, 256>>>(out_w);                                        // 2
    // merged qkv+z projection -> g_mixed, g_z   (profiled slot)
    gemm_mma<0><<<dim3(NBIG / 128, (BB * TT) / 128), 256, GSMEM>>>(nullptr);    // 3
    smallproj_kernel<<<BB * TT, 256>>>(hs, b_w, a_w, dt_bias, A_log);           // 4
    conv_kernel<<<dim3(CDIM / 256, TT / 128, BB), 256>>>(conv_w);               // 5
    scan_kernel<<<dim3(4, NH, BB), 256>>>();                                    // 6
    normgate_kernel<<<BB * TT, 256>>>(norm_w);                                  // 7
    gemm_mma<1><<<dim3(HIDN / 128, (BB * TT) / 128), 256, GSMEM>>>(out);        // 8
}

// round 13
// speedup vs baseline: 1.0338x; 1.0338x over previous
#include <cuda_runtime.h>
#include <cuda_bf16.h>
#include <math.h>
#include <stdint.h>

// Problem constants
#define BB   4
#define TT   1024
#define HIDN 1024
#define NH   8
#define CDIM 3072   // 2*H*DK + H*DV
#define NBIG 4096   // merged N: qkv (3072) + z (1024)
#define KPHY 2048   // physical row: [hi(1024) | lo(1024)]
#define K3   3072   // logical tripled K

// ---------------------------------------------------------------------------
// Scratch (device globals; allocation is forbidden)
// ---------------------------------------------------------------------------
__device__ float g_mixed[(size_t)BB * TT * CDIM];
__device__ float g_qkvc [(size_t)BB * TT * CDIM];
__device__ float g_z    [(size_t)BB * TT * HIDN];
__device__ float g_opre [(size_t)BB * TT * HIDN];
__device__ float g_alpha[(size_t)BB * NH * TT];
__device__ float g_beta [(size_t)BB * NH * TT];

// split-bf16 operands, physical [hi|lo] rows (logical K=3072 via section remap)
__device__ __nv_bfloat16 g_A3hs [(size_t)BB * TT * KPHY];
__device__ __nv_bfloat16 g_A3og [(size_t)BB * TT * KPHY];
__device__ __nv_bfloat16 g_B3big[(size_t)NBIG * KPHY];
__device__ __nv_bfloat16 g_B3out[(size_t)HIDN * KPHY];

// ---------------------------------------------------------------------------
// Base-ISA helpers (sm_80+ only: harness PTX targets compute_103, no 'a').
// ---------------------------------------------------------------------------
__device__ __forceinline__ uint32_t smem_u32(const void* p) {
    return (uint32_t)__cvta_generic_to_shared(p);
}
__device__ __forceinline__ void cp_async16(uint32_t dst, const void* src) {
    asm volatile("cp.async.cg.shared.global [%0], [%1], 16;" :: "r"(dst), "l"(src) : "memory");
}
#define CP_COMMIT() asm volatile("cp.async.commit_group;" ::: "memory")
#define CP_WAIT1()  asm volatile("cp.async.wait_group 1;" ::: "memory")

__device__ __forceinline__ void ldsm_x4(uint32_t* r, uint32_t addr) {
    asm volatile("ldmatrix.sync.aligned.m8n8.x4.shared.b16 {%0,%1,%2,%3}, [%4];"
                 : "=r"(r[0]), "=r"(r[1]), "=r"(r[2]), "=r"(r[3]) : "r"(addr));
}
__device__ __forceinline__ void mma16816(float* c, const uint32_t* a, uint32_t b0, uint32_t b1) {
    asm volatile("mma.sync.aligned.m16n8k16.row.col.f32.bf16.bf16.f32 "
                 "{%0,%1,%2,%3}, {%4,%5,%6,%7}, {%8,%9}, {%0,%1,%2,%3};"
                 : "+f"(c[0]), "+f"(c[1]), "+f"(c[2]), "+f"(c[3])
                 : "r"(a[0]), "r"(a[1]), "r"(a[2]), "r"(a[3]), "r"(b0), "r"(b1));
}

// hi/lo split helpers
__device__ __forceinline__ void split_bf16(float x, __nv_bfloat16& h, __nv_bfloat16& l) {
    h = __float2bfloat16_rn(x);
    l = __float2bfloat16_rn(x - __bfloat162float(h));
}
__device__ __forceinline__ void st_bf16x4(__nv_bfloat16* p, __nv_bfloat16 a, __nv_bfloat16 b,
                                          __nv_bfloat16 c, __nv_bfloat16 d) {
    __nv_bfloat162 v0; v0.x = a; v0.y = b;
    __nv_bfloat162 v1; v1.x = c; v1.y = d;
    *(__nv_bfloat162*)(p)     = v0;
    *(__nv_bfloat162*)(p + 2) = v1;
}

// ---------------------------------------------------------------------------
// Operand conversion: fp32 -> [hi|lo] bf16 pair rows (2048 wide)
// ---------------------------------------------------------------------------
__global__ void __launch_bounds__(256) convert_hs_kernel(const float* __restrict__ hs) {
    const int row = blockIdx.x;
    const int c   = threadIdx.x * 4;
    float4 x = *(const float4*)(hs + (size_t)row * 1024 + c);
    __nv_bfloat16 h0, h1, h2, h3, l0, l1, l2, l3;
    split_bf16(x.x, h0, l0); split_bf16(x.y, h1, l1);
    split_bf16(x.z, h2, l2); split_bf16(x.w, h3, l3);
    __nv_bfloat16* dst = g_A3hs + (size_t)row * KPHY + c;
    st_bf16x4(dst,        h0, h1, h2, h3);
    st_bf16x4(dst + 1024, l0, l1, l2, l3);
}

__global__ void __launch_bounds__(256) convert_w_big(const float* __restrict__ qkv_w,
                                                     const float* __restrict__ z_w) {
    const int row = blockIdx.x;
    const int c   = threadIdx.x * 4;
    const float* src = (row < 3072) ? (qkv_w + (size_t)row * 1024)
                                    : (z_w + (size_t)(row - 3072) * 1024);
    float4 x = *(const float4*)(src + c);
    __nv_bfloat16 h0, h1, h2, h3, l0, l1, l2, l3;
    split_bf16(x.x, h0, l0); split_bf16(x.y, h1, l1);
    split_bf16(x.z, h2, l2); split_bf16(x.w, h3, l3);
    __nv_bfloat16* dst = g_B3big + (size_t)row * KPHY + c;
    st_bf16x4(dst,        h0, h1, h2, h3);
    st_bf16x4(dst + 1024, l0, l1, l2, l3);
}

__global__ void __launch_bounds__(256) convert_w_out(const float* __restrict__ src) {
    const int row = blockIdx.x;
    const int c   = threadIdx.x * 4;
    float4 x = *(const float4*)(src + (size_t)row * 1024 + c);
    __nv_bfloat16 h0, h1, h2, h3, l0, l1, l2, l3;
    split_bf16(x.x, h0, l0); split_bf16(x.y, h1, l1);
    split_bf16(x.z, h2, l2); split_bf16(x.w, h3, l3);
    __nv_bfloat16* dst = g_B3out + (size_t)row * KPHY + c;
    st_bf16x4(dst,        h0, h1, h2, h3);
    st_bf16x4(dst + 1024, l0, l1, l2, l3);
}

// ---------------------------------------------------------------------------
// HMMA GEMM (NT) — EXACT R11 configuration (measured best: 357us for WHICH=0).
// 128x128 tile, BK=32, double-buffered static smem (80B stride), 256 threads,
// warp tile 64x32, logical K=3072 via section remap on the load offsets.
//   WHICH 0: A3hs x B3big (N=4096) -> cols<3072 g_mixed, else g_z
//   WHICH 1: A3og x B3out (N=1024) -> Cext
// ---------------------------------------------------------------------------
template <int WHICH>
__global__ void __launch_bounds__(256) gemm_mma(float* __restrict__ Cext) {
    const __nv_bfloat16* A = WHICH ? g_A3og : g_A3hs;
    const __nv_bfloat16* B = WHICH ? g_B3out : g_B3big;

    __shared__ __nv_bfloat16 As[2][128][40];
    __shared__ __nv_bfloat16 Bs[2][128][40];

    const int tid  = threadIdx.x;
    const int bn   = blockIdx.x * 128;
    const int bm   = blockIdx.y * 128;
    const int warp = tid >> 5, lane = tid & 31;
    const int wm   = (warp >> 2) * 64;
    const int wn   = (warp & 3) * 32;

    float acc[4][4][4];
#pragma unroll
    for (int im = 0; im < 4; im++)
#pragma unroll
        for (int in = 0; in < 4; in++)
#pragma unroll
            for (int r = 0; r < 4; r++) acc[im][in][r] = 0.f;

    const int lr = tid >> 2;
    const int kc = tid & 3;
    const __nv_bfloat16* Ag0 = A + (size_t)(bm + lr)      * KPHY + kc * 8;
    const __nv_bfloat16* Ag1 = A + (size_t)(bm + lr + 64) * KPHY + kc * 8;
    const __nv_bfloat16* Bg0 = B + (size_t)(bn + lr)      * KPHY + kc * 8;
    const __nv_bfloat16* Bg1 = B + (size_t)(bn + lr + 64) * KPHY + kc * 8;

    const uint32_t aS = smem_u32(&As[0][0][0]);
    const uint32_t bS = smem_u32(&Bs[0][0][0]);
    const uint32_t BUF = 128 * 80;
    const uint32_t dA0 = lr * 80 + kc * 16;
    const uint32_t dA1 = (lr + 64) * 80 + kc * 16;

    // logical K=3072 -> physical offsets: A [hi,lo,hi], B [hi,hi,lo]
    auto aoff = [](int k0) { int sec = k0 >> 10, rem = k0 & 1023; return (sec == 1) ? 1024 + rem : rem; };
    auto boff = [](int k0) { int sec = k0 >> 10, rem = k0 & 1023; return (sec == 2) ? 1024 + rem : rem; };

#define LOAD_TILE(buf, k0)                                          \
    do {                                                            \
        const int ao = aoff(k0), bo = boff(k0);                     \
        cp_async16(aS + (buf) * BUF + dA0, Ag0 + ao);               \
        cp_async16(aS + (buf) * BUF + dA1, Ag1 + ao);               \
        cp_async16(bS + (buf) * BUF + dA0, Bg0 + bo);               \
        cp_async16(bS + (buf) * BUF + dA1, Bg1 + bo);               \
        CP_COMMIT();                                                \
    } while (0)

    LOAD_TILE(0, 0);
    LOAD_TILE(1, 32);

    const uint32_t aFrag = aS + (wm + (lane & 15)) * 80 + (lane >> 4) * 16;
    const uint32_t bFrag = bS + (wn + (lane & 15)) * 80 + (lane >> 4) * 16;

    const int NT = K3 / 32;   // 96
    for (int s = 0; s < NT; s++) {
        const int buf = s & 1;
        CP_WAIT1();
        __syncthreads();

#pragma unroll
        for (int ks = 0; ks < 32; ks += 16) {
            uint32_t bfr[2][4];
            ldsm_x4(bfr[0], bFrag + buf * BUF + ks * 2);
            ldsm_x4(bfr[1], bFrag + buf * BUF + 16 * 80 + ks * 2);
#pragma unroll
            for (int im = 0; im < 4; im++) {
                uint32_t afr[4];
                ldsm_x4(afr, aFrag + buf * BUF + im * (16 * 80) + ks * 2);
                mma16816(acc[im][0], afr, bfr[0][0], bfr[0][2]);
                mma16816(acc[im][1], afr, bfr[0][1], bfr[0][3]);
                mma16816(acc[im][2], afr, bfr[1][0], bfr[1][2]);
                mma16816(acc[im][3], afr, bfr[1][1], bfr[1][3]);
            }
        }

        __syncthreads();
        if (s + 2 < NT) LOAD_TILE(buf, (s + 2) * 32);
    }
#undef LOAD_TILE

    float* Cb; int stride, cb;
    if (WHICH == 1)     { Cb = Cext;    stride = 1024; cb = bn; }
    else if (bn < 3072) { Cb = g_mixed; stride = 3072; cb = bn; }
    else                { Cb = g_z;     stride = 1024; cb = bn - 3072; }

    const int er = lane >> 2;
    const int ec = (lane & 3) * 2;
#pragma unroll
    for (int im = 0; im < 4; im++) {
#pragma unroll
        for (int in = 0; in < 4; in++) {
            const int r0  = bm + wm + im * 16 + er;
            const int col = cb + wn + in * 8 + ec;
            *(float2*)&Cb[(size_t)r0 * stride + col]       = make_float2(acc[im][in][0], acc[im][in][1]);
            *(float2*)&Cb[(size_t)(r0 + 8) * stride + col] = make_float2(acc[im][in][2], acc[im][in][3]);
        }
    }
}

// ---------------------------------------------------------------------------
// b/a projections + beta / alpha (fp32: alpha feeds exp())
// ---------------------------------------------------------------------------
__global__ void __launch_bounds__(256) smallproj_kernel(const float* __restrict__ hs,
                                                        const float* __restrict__ b_w,
                                                        const float* __restrict__ a_w,
                                                        const float* __restrict__ dt_bias,
                                                        const float* __restrict__ A_log) {
    __shared__ float sh[1024];
    const int bt  = blockIdx.x;
    const int tid = threadIdx.x;
    const float* row = hs + (size_t)bt * 1024;
    *(float4*)&sh[tid * 4] = *(const float4*)(row + tid * 4);
    __syncthreads();

    const int h = tid >> 5, lane = tid & 31;
    const float* bw = b_w + h * 1024;
    const float* aw = a_w + h * 1024;
    float sb = 0.f, sa = 0.f;
#pragma unroll
    for (int i = 0; i < 8; i++) {
        int idx = lane * 4 + i * 128;
        float4 x  = *(float4*)&sh[idx];
        float4 wb = *(const float4*)(bw + idx);
        float4 wa = *(const float4*)(aw + idx);
        sb += x.x * wb.x + x.y * wb.y + x.z * wb.z + x.w * wb.w;
        sa += x.x * wa.x + x.y * wa.y + x.z * wa.z + x.w * wa.w;
    }
#pragma unroll
    for (int m = 16; m; m >>= 1) {
        sb += __shfl_xor_sync(0xffffffffu, sb, m);
        sa += __shfl_xor_sync(0xffffffffu, sa, m);
    }
    if (lane == 0) {
        float beta = 1.f / (1.f + expf(-sb));
        float x  = sa + dt_bias[h];
        float sp = (x > 20.f) ? x : log1pf(expf(x));
        float g  = -expf(A_log[h]) * sp;
        int b = bt >> 10, t = bt & 1023;
        g_alpha[((b * NH + h) << 10) + t] = expf(g);
        g_beta [((b * NH + h) << 10) + t] = beta;
    }
}

// ---------------------------------------------------------------------------
// Causal depthwise conv1d (K=4)
// ---------------------------------------------------------------------------
__global__ void __launch_bounds__(256) conv_kernel(const float* __restrict__ conv_w) {
    const int c  = blockIdx.x * 256 + threadIdx.x;
    const int t0 = blockIdx.y * 128;
    const int b  = blockIdx.z;
    float4 w4 = *(const float4*)(conv_w + c * 4);
    const float* xin  = g_mixed + (size_t)b * TT * CDIM + c;
    float*       yout = g_qkvc  + (size_t)b * TT * CDIM + c;
    float x0 = (t0 >= 3) ? xin[(size_t)(t0 - 3) * CDIM] : 0.f;
    float x1 = (t0 >= 2) ? xin[(size_t)(t0 - 2) * CDIM] : 0.f;
    float x2 = (t0 >= 1) ? xin[(size_t)(t0 - 1) * CDIM] : 0.f;
#pragma unroll 4
    for (int t = t0; t < t0 + 128; t++) {
        float x3 = xin[(size_t)t * CDIM];
        yout[(size_t)t * CDIM] = w4.x * x0 + w4.y * x1 + w4.z * x2 + w4.w * x3;
        x0 = x1; x1 = x2; x2 = x3;
    }
}

// ---------------------------------------------------------------------------
// Gated delta-rule scan v4: 512 threads (4 warps/SMSP for latency hiding).
// grid = (4 dv-chunks, H, B) = 128 CTAs. Warp = 2 cols x 16 dk-splits
// (split = lane&15, 8 dk each; S[8]/thread). smem padded 12 words/split:
// compute-phase LDS.128 offsets mod 32 = {0,12,24,4,16,28,8,20} -> conflict-free.
// Reductions: shfl xor over lane bits 0..3.
// ---------------------------------------------------------------------------
__global__ void __launch_bounds__(512) scan_kernel() {
    __shared__ float sk[16][192];   // 16 splits * 12 words
    __shared__ float sq[16][192];
    __shared__ float sv[16][32];
    __shared__ float so[16][32];
    __shared__ float sal[16];
    __shared__ float sbe[16];

    const int tid   = threadIdx.x;
    const int chunk = blockIdx.x;
    const int h     = blockIdx.y;
    const int b     = blockIdx.z;

    const int lane  = tid & 31;
    const int w     = tid >> 5;              // warp 0..15 (also staging time-row)
    const int split = lane & 15;             // dk split (8 each)
    const int col   = w * 2 + (lane >> 4);   // 0..31 within chunk
    const int kbp   = split * 12;            // padded smem base

    const float* qbase = g_qkvc + (size_t)b * TT * CDIM + h * 128;
    const float* abase = g_alpha + ((size_t)(b * NH + h) << 10);
    const float* bbase = g_beta  + ((size_t)(b * NH + h) << 10);

    float S[8];
#pragma unroll
    for (int j = 0; j < 8; j++) S[j] = 0.f;

    // staging: warp w loads time-row w; lane -> float4 at data col lane*4
    const int cc   = lane * 4;
    const int dpad = (cc >> 3) * 12 + (cc & 7);

    float4 pq, pk, pv;
    float pal = 0.f, pbe = 0.f;
    {
        const float* row = qbase + (size_t)w * CDIM;
        pq = *(const float4*)(row + cc);
        pk = *(const float4*)(row + 1024 + cc);
        if (lane < 8) pv = *(const float4*)(row + 2048 + chunk * 32 + lane * 4);
        if (tid < 16) { pal = abase[tid]; pbe = bbase[tid]; }
    }

    for (int t0 = 0; t0 < TT; t0 += 16) {
        __syncthreads();   // prior block's compute done
        if (t0 > 0) {      // flush previous outputs (512 values, 1/thread)
            int tt = tid >> 5, dd = tid & 31;
            g_opre[(((size_t)(b * TT + (t0 - 16) + tt)) * NH + h) * 128 + chunk * 32 + dd] = so[tt][dd];
        }
        *(float4*)&sq[w][dpad] = pq;
        *(float4*)&sk[w][dpad] = pk;
        if (lane < 8) *(float4*)&sv[w][lane * 4] = pv;
        if (tid < 16) { sal[tid] = pal; sbe[tid] = pbe; }
        __syncthreads();

        if (t0 + 16 < TT) {   // prefetch next block (overlaps compute)
            const float* row = qbase + (size_t)(t0 + 16 + w) * CDIM;
            pq = *(const float4*)(row + cc);
            pk = *(const float4*)(row + 1024 + cc);
            if (lane < 8) pv = *(const float4*)(row + 2048 + chunk * 32 + lane * 4);
            if (tid < 16) { pal = abase[t0 + 16 + tid]; pbe = bbase[t0 + 16 + tid]; }
        }

#pragma unroll 2
        for (int tt = 0; tt < 16; tt++) {
            const float alpha = sal[tt];
            const float beta  = sbe[tt];

            float kr[8];
            *(float4*)&kr[0] = *(float4*)&sk[tt][kbp];
            *(float4*)&kr[4] = *(float4*)&sk[tt][kbp + 4];

            float kva = 0.f, kvb = 0.f, kvc = 0.f, kvd = 0.f;
#pragma unroll
            for (int j = 0; j < 8; j += 4) {
                S[j]     *= alpha; kva = fmaf(kr[j],     S[j],     kva);
                S[j + 1] *= alpha; kvb = fmaf(kr[j + 1], S[j + 1], kvb);
                S[j + 2] *= alpha; kvc = fmaf(kr[j + 2], S[j + 2], kvc);
                S[j + 3] *= alpha; kvd = fmaf(kr[j + 3], S[j + 3], kvd);
            }
            float kv = (kva + kvb) + (kvc + kvd);
            kv += __shfl_xor_sync(0xffffffffu, kv, 1);
            kv += __shfl_xor_sync(0xffffffffu, kv, 2);
            kv += __shfl_xor_sync(0xffffffffu, kv, 4);
            kv += __shfl_xor_sync(0xffffffffu, kv, 8);

            const float wv = (sv[tt][col] - kv) * beta;

            float qr[8];
            *(float4*)&qr[0] = *(float4*)&sq[tt][kbp];
            *(float4*)&qr[4] = *(float4*)&sq[tt][kbp + 4];

            float oa = 0.f, ob = 0.f, oc = 0.f, od = 0.f;
#pragma unroll
            for (int j = 0; j < 8; j += 4) {
                S[j]     = fmaf(kr[j],     wv, S[j]);     oa = fmaf(qr[j],     S[j],     oa);
                S[j + 1] = fmaf(kr[j + 1], wv, S[j + 1]); ob = fmaf(qr[j + 1], S[j + 1], ob);
                S[j + 2] = fmaf(kr[j + 2], wv, S[j + 2]); oc = fmaf(qr[j + 2], S[j + 2], oc);
                S[j + 3] = fmaf(kr[j + 3], wv, S[j + 3]); od = fmaf(qr[j + 3], S[j + 3], od);
            }
            float o = (oa + ob) + (oc + od);
            o += __shfl_xor_sync(0xffffffffu, o, 1);
            o += __shfl_xor_sync(0xffffffffu, o, 2);
            o += __shfl_xor_sync(0xffffffffu, o, 4);
            o += __shfl_xor_sync(0xffffffffu, o, 8);
            if (split == 0) so[tt][col] = o;
        }
    }

    __syncthreads();
    {
        int tt = tid >> 5, dd = tid & 31;
        g_opre[(((size_t)(b * TT + (TT - 16) + tt)) * NH + h) * 128 + chunk * 32 + dd] = so[tt][dd];
    }
}

// ---------------------------------------------------------------------------
// Gated RMSNorm fused with [hi|lo] bf16 emission for the out GEMM A operand
// ---------------------------------------------------------------------------
__global__ void __launch_bounds__(256) normgate_kernel(const float* __restrict__ norm_w) {
    const int bt   = blockIdx.x;
    const int h    = threadIdx.x >> 5;
    const int lane = threadIdx.x & 31;

    const size_t obase = ((size_t)bt * NH + h) * 128 + lane * 4;
    float4 o4 = *(const float4*)(g_opre + obase);
    float ss = o4.x * o4.x + o4.y * o4.y + o4.z * o4.z + o4.w * o4.w;
#pragma unroll
    for (int m = 16; m; m >>= 1) ss += __shfl_xor_sync(0xffffffffu, ss, m);
    const float scale = rsqrtf(ss * (1.f / 128.f) + 1e-6f);

    const size_t zbase = (size_t)bt * 1024 + h * 128 + lane * 4;
    float4 z4 = *(const float4*)(g_z + zbase);
    float4 nw = *(const float4*)(norm_w + lane * 4);
    float rx = o4.x * scale * nw.x * (z4.x / (1.f + expf(-z4.x)));
    float ry = o4.y * scale * nw.y * (z4.y / (1.f + expf(-z4.y)));
    float rz = o4.z * scale * nw.z * (z4.z / (1.f + expf(-z4.z)));
    float rw = o4.w * scale * nw.w * (z4.w / (1.f + expf(-z4.w)));

    __nv_bfloat16 h0, h1, h2, h3, l0, l1, l2, l3;
    split_bf16(rx, h0, l0); split_bf16(ry, h1, l1);
    split_bf16(rz, h2, l2); split_bf16(rw, h3, l3);
    __nv_bfloat16* dst = g_A3og + (size_t)bt * KPHY + h * 128 + lane * 4;
    st_bf16x4(dst,        h0, h1, h2, h3);
    st_bf16x4(dst + 1024, l0, l1, l2, l3);
}

// ---------------------------------------------------------------------------
// kernel_launch  (gemm_mma<0> kept at launch index 3 = the profiled slot)
// ---------------------------------------------------------------------------
extern "C" void kernel_launch(void* const* d_in, const int* in_sizes, int n_in,
                              void* d_out, int out_size) {
    const float* hs      = (const float*)d_in[0];
    const float* qkv_w   = (const float*)d_in[1];
    const float* z_w     = (const float*)d_in[2];
    const float* b_w     = (const float*)d_in[3];
    const float* a_w     = (const float*)d_in[4];
    const float* conv_w  = (const float*)d_in[5];
    const float* dt_bias = (const float*)d_in[6];
    const float* A_log   = (const float*)d_in[7];
    const float* norm_w  = (const float*)d_in[8];
    const float* out_w   = (const float*)d_in[9];
    float* out = (float*)d_out;

    convert_hs_kernel<<<BB * TT, 256>>>(hs);                                    // 0
    convert_w_big<<<NBIG, 256>>>(qkv_w, z_w);                                   // 1
    convert_w_out<<<HIDN, 256>>>(out_w);                                        // 2
    // merged qkv+z projection -> g_mixed, g_z   (profiled slot)
    gemm_mma<0><<<dim3(NBIG / 128, (BB * TT) / 128), 256>>>(nullptr);           // 3
    smallproj_kernel<<<BB * TT, 256>>>(hs, b_w, a_w, dt_bias, A_log);           // 4
    conv_kernel<<<dim3(CDIM / 256, TT / 128, BB), 256>>>(conv_w);               // 5
    scan_kernel<<<dim3(4, NH, BB), 512>>>();                                    // 6
    normgate_kernel<<<BB * TT, 256>>>(norm_w);                                  // 7
    gemm_mma<1><<<dim3(HIDN / 128, (BB * TT) / 128), 256>>>(out);               // 8
}

// round 15
// speedup vs baseline: 1.1607x; 1.1227x over previous
#include <cuda_runtime.h>
#include <cuda_bf16.h>
#include <math.h>
#include <stdint.h>

// Problem constants
#define BB   4
#define TT   1024
#define HIDN 1024
#define NH   8
#define CDIM 3072   // 2*H*DK + H*DV
#define NBIG 4096   // merged N: qkv (3072) + z (1024)
#define K3   3072   // tripled K for split-bf16 GEMM

// GEMM pipeline geometry (3-stage ring, R11 layout per stage)
#define GBUF  20480                 // one stage: A(128x80B) + B(128x80B)
#define GSMEM (3 * GBUF)            // 61440 bytes dynamic

// ---------------------------------------------------------------------------
// Scratch (device globals; allocation is forbidden)
// ---------------------------------------------------------------------------
__device__ float g_mixed[(size_t)BB * TT * CDIM];
__device__ float g_qkvc [(size_t)BB * TT * CDIM];
__device__ float g_z    [(size_t)BB * TT * HIDN];
__device__ float g_opre [(size_t)BB * TT * HIDN];
__device__ float g_alpha[(size_t)BB * NH * TT];
__device__ float g_beta [(size_t)BB * NH * TT];

// split-bf16 operands (K-tripled): A = [hi, lo, hi], B = [hi, hi, lo]
__device__ __nv_bfloat16 g_A3hs [(size_t)BB * TT * K3];   // hidden_states
__device__ __nv_bfloat16 g_A3og [(size_t)BB * TT * K3];   // gated/normed output
__device__ __nv_bfloat16 g_B3big[(size_t)NBIG * K3];      // [qkv_w ; z_w]
__device__ __nv_bfloat16 g_B3out[(size_t)HIDN * K3];      // out_w

// ---------------------------------------------------------------------------
// Base-ISA helpers (sm_80+ only: harness PTX targets compute_103, no 'a').
// ---------------------------------------------------------------------------
__device__ __forceinline__ uint32_t smem_u32(const void* p) {
    return (uint32_t)__cvta_generic_to_shared(p);
}
__device__ __forceinline__ void cp_async16(uint32_t dst, const void* src) {
    asm volatile("cp.async.cg.shared.global [%0], [%1], 16;" :: "r"(dst), "l"(src) : "memory");
}
#define CP_COMMIT() asm volatile("cp.async.commit_group;" ::: "memory")
#define CP_WAIT1()  asm volatile("cp.async.wait_group 1;" ::: "memory")

__device__ __forceinline__ void ldsm_x4(uint32_t* r, uint32_t addr) {
    asm volatile("ldmatrix.sync.aligned.m8n8.x4.shared.b16 {%0,%1,%2,%3}, [%4];"
                 : "=r"(r[0]), "=r"(r[1]), "=r"(r[2]), "=r"(r[3]) : "r"(addr));
}
__device__ __forceinline__ void mma16816(float* c, const uint32_t* a, uint32_t b0, uint32_t b1) {
    asm volatile("mma.sync.aligned.m16n8k16.row.col.f32.bf16.bf16.f32 "
                 "{%0,%1,%2,%3}, {%4,%5,%6,%7}, {%8,%9}, {%0,%1,%2,%3};"
                 : "+f"(c[0]), "+f"(c[1]), "+f"(c[2]), "+f"(c[3])
                 : "r"(a[0]), "r"(a[1]), "r"(a[2]), "r"(a[3]), "r"(b0), "r"(b1));
}

// hi/lo split helpers
__device__ __forceinline__ void split_bf16(float x, __nv_bfloat16& h, __nv_bfloat16& l) {
    h = __float2bfloat16_rn(x);
    l = __float2bfloat16_rn(x - __bfloat162float(h));
}
__device__ __forceinline__ void st_bf16x4(__nv_bfloat16* p, __nv_bfloat16 a, __nv_bfloat16 b,
                                          __nv_bfloat16 c, __nv_bfloat16 d) {
    __nv_bfloat162 v0; v0.x = a; v0.y = b;
    __nv_bfloat162 v1; v1.x = c; v1.y = d;
    *(__nv_bfloat162*)(p)     = v0;
    *(__nv_bfloat162*)(p + 2) = v1;
}

// ---------------------------------------------------------------------------
// FUSED: hs conversion (fp32 -> [hi,lo,hi] bf16) + b/a projections.
// Both consumed the same hs row; one load feeds both. Bodies are verbatim
// from the two proven kernels.
// ---------------------------------------------------------------------------
__global__ void __launch_bounds__(256) fused_hs_kernel(const float* __restrict__ hs,
                                                       const float* __restrict__ b_w,
                                                       const float* __restrict__ a_w,
                                                       const float* __restrict__ dt_bias,
                                                       const float* __restrict__ A_log) {
    __shared__ float sh[1024];
    const int bt  = blockIdx.x;
    const int tid = threadIdx.x;
    const int c   = tid * 4;

    float4 x = *(const float4*)(hs + (size_t)bt * 1024 + c);
    *(float4*)&sh[c] = x;

    // convert part
    {
        __nv_bfloat16 h0, h1, h2, h3, l0, l1, l2, l3;
        split_bf16(x.x, h0, l0); split_bf16(x.y, h1, l1);
        split_bf16(x.z, h2, l2); split_bf16(x.w, h3, l3);
        __nv_bfloat16* dst = g_A3hs + (size_t)bt * K3 + c;
        st_bf16x4(dst,        h0, h1, h2, h3);
        st_bf16x4(dst + 1024, l0, l1, l2, l3);
        st_bf16x4(dst + 2048, h0, h1, h2, h3);
    }
    __syncthreads();

    // smallproj part (warp per head)
    const int h = tid >> 5, lane = tid & 31;
    const float* bw = b_w + h * 1024;
    const float* aw = a_w + h * 1024;
    float sb = 0.f, sa = 0.f;
#pragma unroll
    for (int i = 0; i < 8; i++) {
        int idx = lane * 4 + i * 128;
        float4 xx = *(float4*)&sh[idx];
        float4 wb = *(const float4*)(bw + idx);
        float4 wa = *(const float4*)(aw + idx);
        sb += xx.x * wb.x + xx.y * wb.y + xx.z * wb.z + xx.w * wb.w;
        sa += xx.x * wa.x + xx.y * wa.y + xx.z * wa.z + xx.w * wa.w;
    }
#pragma unroll
    for (int m = 16; m; m >>= 1) {
        sb += __shfl_xor_sync(0xffffffffu, sb, m);
        sa += __shfl_xor_sync(0xffffffffu, sa, m);
    }
    if (lane == 0) {
        float beta = 1.f / (1.f + expf(-sb));
        float xg  = sa + dt_bias[h];
        float sp = (xg > 20.f) ? xg : log1pf(expf(xg));
        float g  = -expf(A_log[h]) * sp;
        int b = bt >> 10, t = bt & 1023;
        g_alpha[((b * NH + h) << 10) + t] = expf(g);
        g_beta [((b * NH + h) << 10) + t] = beta;
    }
}

// ---------------------------------------------------------------------------
// Weight conversions (R11-exact, two kernels)
// ---------------------------------------------------------------------------
__global__ void __launch_bounds__(256) convert_w_big(const float* __restrict__ qkv_w,
                                                     const float* __restrict__ z_w) {
    const int row = blockIdx.x;
    const int c   = threadIdx.x * 4;
    const float* src = (row < 3072) ? (qkv_w + (size_t)row * 1024)
                                    : (z_w + (size_t)(row - 3072) * 1024);
    float4 x = *(const float4*)(src + c);
    __nv_bfloat16 h0, h1, h2, h3, l0, l1, l2, l3;
    split_bf16(x.x, h0, l0); split_bf16(x.y, h1, l1);
    split_bf16(x.z, h2, l2); split_bf16(x.w, h3, l3);
    __nv_bfloat16* dst = g_B3big + (size_t)row * K3 + c;
    st_bf16x4(dst,        h0, h1, h2, h3);
    st_bf16x4(dst + 1024, h0, h1, h2, h3);
    st_bf16x4(dst + 2048, l0, l1, l2, l3);
}

__global__ void __launch_bounds__(256) convert_w_out(const float* __restrict__ src) {
    const int row = blockIdx.x;
    const int c   = threadIdx.x * 4;
    float4 x = *(const float4*)(src + (size_t)row * 1024 + c);
    __nv_bfloat16 h0, h1, h2, h3, l0, l1, l2, l3;
    split_bf16(x.x, h0, l0); split_bf16(x.y, h1, l1);
    split_bf16(x.z, h2, l2); split_bf16(x.w, h3, l3);
    __nv_bfloat16* dst = g_B3out + (size_t)row * K3 + c;
    st_bf16x4(dst,        h0, h1, h2, h3);
    st_bf16x4(dst + 1024, h0, h1, h2, h3);
    st_bf16x4(dst + 2048, l0, l1, l2, l3);
}

// ---------------------------------------------------------------------------
// HMMA GEMM (NT): R11 tile/layout/loader, upgraded to a 3-stage cp.async ring.
// 128x128 tile, BK=32, 256 threads, warp tile 64x32, 80B smem rows (as R11).
// Per stage: WAIT1 -> ONE __syncthreads -> issue load(s+2) -> compute(s).
//   - wait_group 1 at top of iter s: loads 0..s+1 committed -> load s complete.
//   - stage (s+2)%3 was last read by compute(s-1); the sync orders that.
//   WHICH 0: A3hs x B3big (N=4096) -> cols<3072 g_mixed, else g_z
//   WHICH 1: A3og x B3out (N=1024) -> Cext
// ---------------------------------------------------------------------------
template <int WHICH>
__global__ void __launch_bounds__(256) gemm_mma(float* __restrict__ Cext) {
    const __nv_bfloat16* A = WHICH ? g_A3og : g_A3hs;
    const __nv_bfloat16* B = WHICH ? g_B3out : g_B3big;

    extern __shared__ __align__(16) char smem[];
    const uint32_t sB = smem_u32(smem);

    const int tid  = threadIdx.x;
    const int bn   = blockIdx.x * 128;
    const int bm   = blockIdx.y * 128;
    const int warp = tid >> 5, lane = tid & 31;
    const int wm   = (warp >> 2) * 64;
    const int wn   = (warp & 3) * 32;

    float acc[4][4][4];
#pragma unroll
    for (int im = 0; im < 4; im++)
#pragma unroll
        for (int in = 0; in < 4; in++)
#pragma unroll
            for (int r = 0; r < 4; r++) acc[im][in][r] = 0.f;

    // loader mapping (R11-exact)
    const int lr = tid >> 2;
    const int kc = tid & 3;
    const __nv_bfloat16* Ag0 = A + (size_t)(bm + lr)      * K3 + kc * 8;
    const __nv_bfloat16* Ag1 = A + (size_t)(bm + lr + 64) * K3 + kc * 8;
    const __nv_bfloat16* Bg0 = B + (size_t)(bn + lr)      * K3 + kc * 8;
    const __nv_bfloat16* Bg1 = B + (size_t)(bn + lr + 64) * K3 + kc * 8;

    const uint32_t dA0 = lr * 80 + kc * 16;
    const uint32_t dA1 = (lr + 64) * 80 + kc * 16;

#define LOAD_STAGE(base, k0)                                  \
    do {                                                      \
        cp_async16((base) + dA0,         Ag0 + (k0));         \
        cp_async16((base) + dA1,         Ag1 + (k0));         \
        cp_async16((base) + 10240 + dA0, Bg0 + (k0));         \
        cp_async16((base) + 10240 + dA1, Bg1 + (k0));         \
        CP_COMMIT();                                          \
    } while (0)

    LOAD_STAGE(sB, 0);
    LOAD_STAGE(sB + GBUF, 32);

    // fragment offsets within a stage (R11-exact layout; B block at +10240)
    const uint32_t aFo = (wm + (lane & 15)) * 80 + (lane >> 4) * 16;
    const uint32_t bFo = 10240 + (wn + (lane & 15)) * 80 + (lane >> 4) * 16;

    int cur = 0;
    const int NT = K3 / 32;   // 96
    for (int s = 0; s < NT; s++) {
        CP_WAIT1();           // load s complete
        __syncthreads();      // data visible + prior compute done (buffer reuse safe)

        if (s + 2 < NT) {
            int nxt = cur + 2; if (nxt >= 3) nxt -= 3;
            LOAD_STAGE(sB + nxt * GBUF, (s + 2) * 32);   // ~2-stage lead
        }

        const uint32_t base = sB + cur * GBUF;
        const uint32_t aF = base + aFo;
        const uint32_t bF = base + bFo;

#pragma unroll
        for (int ks = 0; ks < 32; ks += 16) {
            uint32_t bfr[2][4];
            ldsm_x4(bfr[0], bF + ks * 2);
            ldsm_x4(bfr[1], bF + 16 * 80 + ks * 2);
#pragma unroll
            for (int im = 0; im < 4; im++) {
                uint32_t afr[4];
                ldsm_x4(afr, aF + im * (16 * 80) + ks * 2);
                mma16816(acc[im][0], afr, bfr[0][0], bfr[0][2]);
                mma16816(acc[im][1], afr, bfr[0][1], bfr[0][3]);
                mma16816(acc[im][2], afr, bfr[1][0], bfr[1][2]);
                mma16816(acc[im][3], afr, bfr[1][1], bfr[1][3]);
            }
        }

        cur = (cur == 2) ? 0 : cur + 1;
    }
#undef LOAD_STAGE

    float* Cb; int stride, cb;
    if (WHICH == 1)     { Cb = Cext;    stride = 1024; cb = bn; }
    else if (bn < 3072) { Cb = g_mixed; stride = 3072; cb = bn; }
    else                { Cb = g_z;     stride = 1024; cb = bn - 3072; }

    const int er = lane >> 2;
    const int ec = (lane & 3) * 2;
#pragma unroll
    for (int im = 0; im < 4; im++) {
#pragma unroll
        for (int in = 0; in < 4; in++) {
            const int r0  = bm + wm + im * 16 + er;
            const int col = cb + wn + in * 8 + ec;
            *(float2*)&Cb[(size_t)r0 * stride + col]       = make_float2(acc[im][in][0], acc[im][in][1]);
            *(float2*)&Cb[(size_t)(r0 + 8) * stride + col] = make_float2(acc[im][in][2], acc[im][in][3]);
        }
    }
}

// ---------------------------------------------------------------------------
// Causal depthwise conv1d (K=4)  (R11-exact)
// ---------------------------------------------------------------------------
__global__ void __launch_bounds__(256) conv_kernel(const float* __restrict__ conv_w) {
    const int c  = blockIdx.x * 256 + threadIdx.x;
    const int t0 = blockIdx.y * 128;
    const int b  = blockIdx.z;
    float4 w4 = *(const float4*)(conv_w + c * 4);
    const float* xin  = g_mixed + (size_t)b * TT * CDIM + c;
    float*       yout = g_qkvc  + (size_t)b * TT * CDIM + c;
    float x0 = (t0 >= 3) ? xin[(size_t)(t0 - 3) * CDIM] : 0.f;
    float x1 = (t0 >= 2) ? xin[(size_t)(t0 - 2) * CDIM] : 0.f;
    float x2 = (t0 >= 1) ? xin[(size_t)(t0 - 1) * CDIM] : 0.f;
#pragma unroll 4
    for (int t = t0; t < t0 + 128; t++) {
        float x3 = xin[(size_t)t * CDIM];
        yout[(size_t)t * CDIM] = w4.x * x0 + w4.y * x1 + w4.z * x2 + w4.w * x3;
        x0 = x1; x1 = x2; x2 = x3;
    }
}

// ---------------------------------------------------------------------------
// Gated delta-rule scan (R11-exact v2 body, unroll 2).
// grid = (4 dv-chunks, H, B) = 128 CTAs, 256 threads.
// ---------------------------------------------------------------------------
__global__ void __launch_bounds__(256) scan_kernel() {
    __shared__ float sk[16][160];
    __shared__ float sq[16][160];
    __shared__ float sv[16][32];
    __shared__ float so[16][32];
    __shared__ float sal[16];
    __shared__ float sbe[16];

    const int tid   = threadIdx.x;
    const int chunk = blockIdx.x;
    const int h     = blockIdx.y;
    const int b     = blockIdx.z;

    const int lane  = tid & 31;
    const int w     = tid >> 5;
    const int split = lane & 7;
    const int col   = w * 4 + (lane >> 3);
    const int kbp   = split * 20;

    const float* qbase = g_qkvc + (size_t)b * TT * CDIM + h * 128;
    const float* abase = g_alpha + ((size_t)(b * NH + h) << 10);
    const float* bbase = g_beta  + ((size_t)(b * NH + h) << 10);

    float S[16];
#pragma unroll
    for (int j = 0; j < 16; j++) S[j] = 0.f;

    const int ltt  = tid >> 4;
    const int lseg = tid & 15;
    const int cc0  = lseg * 8;
    const int cc1  = cc0 + 4;
    const int d0   = cc0 + ((cc0 >> 4) << 2);
    const int d1   = cc1 + ((cc1 >> 4) << 2);

    float4 pq0, pq1, pk0, pk1, pv;
    float pal = 0.f, pbe = 0.f;
    {
        const float* row = qbase + (size_t)ltt * CDIM;
        pq0 = *(const float4*)(row + cc0);
        pq1 = *(const float4*)(row + cc1);
        pk0 = *(const float4*)(row + 1024 + cc0);
        pk1 = *(const float4*)(row + 1024 + cc1);
        if (lseg < 8) pv = *(const float4*)(row + 2048 + chunk * 32 + lseg * 4);
        if (tid < 16) { pal = abase[tid]; pbe = bbase[tid]; }
    }

    for (int t0 = 0; t0 < TT; t0 += 16) {
        __syncthreads();
        if (t0 > 0) {
            for (int idx = tid; idx < 512; idx += 256) {
                int tt = idx >> 5, dd = idx & 31;
                g_opre[(((size_t)(b * TT + (t0 - 16) + tt)) * NH + h) * 128 + chunk * 32 + dd] = so[tt][dd];
            }
        }
        *(float4*)&sq[ltt][d0] = pq0;
        *(float4*)&sq[ltt][d1] = pq1;
        *(float4*)&sk[ltt][d0] = pk0;
        *(float4*)&sk[ltt][d1] = pk1;
        if (lseg < 8) *(float4*)&sv[ltt][lseg * 4] = pv;
        if (tid < 16) { sal[tid] = pal; sbe[tid] = pbe; }
        __syncthreads();

        if (t0 + 16 < TT) {
            const float* row = qbase + (size_t)(t0 + 16 + ltt) * CDIM;
            pq0 = *(const float4*)(row + cc0);
            pq1 = *(const float4*)(row + cc1);
            pk0 = *(const float4*)(row + 1024 + cc0);
            pk1 = *(const float4*)(row + 1024 + cc1);
            if (lseg < 8) pv = *(const float4*)(row + 2048 + chunk * 32 + lseg * 4);
            if (tid < 16) { pal = abase[t0 + 16 + tid]; pbe = bbase[t0 + 16 + tid]; }
        }

#pragma unroll 2
        for (int tt = 0; tt < 16; tt++) {
            const float alpha = sal[tt];
            const float beta  = sbe[tt];

            float kr[16];
#pragma unroll
            for (int uu = 0; uu < 4; uu++)
                *(float4*)&kr[uu * 4] = *(float4*)&sk[tt][kbp + uu * 4];

            float kva = 0.f, kvb = 0.f, kvc = 0.f, kvd = 0.f;
#pragma unroll
            for (int j = 0; j < 16; j += 4) {
                S[j]     *= alpha; kva = fmaf(kr[j],     S[j],     kva);
                S[j + 1] *= alpha; kvb = fmaf(kr[j + 1], S[j + 1], kvb);
                S[j + 2] *= alpha; kvc = fmaf(kr[j + 2], S[j + 2], kvc);
                S[j + 3] *= alpha; kvd = fmaf(kr[j + 3], S[j + 3], kvd);
            }
            float kv = (kva + kvb) + (kvc + kvd);
            kv += __shfl_xor_sync(0xffffffffu, kv, 1);
            kv += __shfl_xor_sync(0xffffffffu, kv, 2);
            kv += __shfl_xor_sync(0xffffffffu, kv, 4);

            const float wv = (sv[tt][col] - kv) * beta;

            float qr[16];
#pragma unroll
            for (int uu = 0; uu < 4; uu++)
                *(float4*)&qr[uu * 4] = *(float4*)&sq[tt][kbp + uu * 4];

            float oa = 0.f, ob = 0.f, oc = 0.f, od = 0.f;
#pragma unroll
            for (int j = 0; j < 16; j += 4) {
                S[j]     = fmaf(kr[j],     wv, S[j]);     oa = fmaf(qr[j],     S[j],     oa);
                S[j + 1] = fmaf(kr[j + 1], wv, S[j + 1]); ob = fmaf(qr[j + 1], S[j + 1], ob);
                S[j + 2] = fmaf(kr[j + 2], wv, S[j + 2]); oc = fmaf(qr[j + 2], S[j + 2], oc);
                S[j + 3] = fmaf(kr[j + 3], wv, S[j + 3]); od = fmaf(qr[j + 3], S[j + 3], od);
            }
            float o = (oa + ob) + (oc + od);
            o += __shfl_xor_sync(0xffffffffu, o, 1);
            o += __shfl_xor_sync(0xffffffffu, o, 2);
            o += __shfl_xor_sync(0xffffffffu, o, 4);
            if (split == 0) so[tt][col] = o;
        }
    }

    __syncthreads();
    for (int idx = tid; idx < 512; idx += 256) {
        int tt = idx >> 5, dd = idx & 31;
        g_opre[(((size_t)(b * TT + (TT - 16) + tt)) * NH + h) * 128 + chunk * 32 + dd] = so[tt][dd];
    }
}

// ---------------------------------------------------------------------------
// Gated RMSNorm fused with split-bf16 A-operand emission (R11-exact)
// ---------------------------------------------------------------------------
__global__ void __launch_bounds__(256) normgate_kernel(const float* __restrict__ norm_w) {
    const int bt   = blockIdx.x;
    const int h    = threadIdx.x >> 5;
    const int lane = threadIdx.x & 31;

    const size_t obase = ((size_t)bt * NH + h) * 128 + lane * 4;
    float4 o4 = *(const float4*)(g_opre + obase);
    float ss = o4.x * o4.x + o4.y * o4.y + o4.z * o4.z + o4.w * o4.w;
#pragma unroll
    for (int m = 16; m; m >>= 1) ss += __shfl_xor_sync(0xffffffffu, ss, m);
    const float scale = rsqrtf(ss * (1.f / 128.f) + 1e-6f);

    const size_t zbase = (size_t)bt * 1024 + h * 128 + lane * 4;
    float4 z4 = *(const float4*)(g_z + zbase);
    float4 nw = *(const float4*)(norm_w + lane * 4);
    float rx = o4.x * scale * nw.x * (z4.x / (1.f + expf(-z4.x)));
    float ry = o4.y * scale * nw.y * (z4.y / (1.f + expf(-z4.y)));
    float rz = o4.z * scale * nw.z * (z4.z / (1.f + expf(-z4.z)));
    float rw = o4.w * scale * nw.w * (z4.w / (1.f + expf(-z4.w)));

    __nv_bfloat16 h0, h1, h2, h3, l0, l1, l2, l3;
    split_bf16(rx, h0, l0); split_bf16(ry, h1, l1);
    split_bf16(rz, h2, l2); split_bf16(rw, h3, l3);
    __nv_bfloat16* dst = g_A3og + (size_t)bt * K3 + h * 128 + lane * 4;
    st_bf16x4(dst,        h0, h1, h2, h3);
    st_bf16x4(dst + 1024, l0, l1, l2, l3);
    st_bf16x4(dst + 2048, h0, h1, h2, h3);
}

// ---------------------------------------------------------------------------
// kernel_launch  (gemm_mma<0> kept at launch index 3 = the profiled slot)
// ---------------------------------------------------------------------------
extern "C" void kernel_launch(void* const* d_in, const int* in_sizes, int n_in,
                              void* d_out, int out_size) {
    const float* hs      = (const float*)d_in[0];
    const float* qkv_w   = (const float*)d_in[1];
    const float* z_w     = (const float*)d_in[2];
    const float* b_w     = (const float*)d_in[3];
    const float* a_w     = (const float*)d_in[4];
    const float* conv_w  = (const float*)d_in[5];
    const float* dt_bias = (const float*)d_in[6];
    const float* A_log   = (const float*)d_in[7];
    const float* norm_w  = (const float*)d_in[8];
    const float* out_w   = (const float*)d_in[9];
    float* out = (float*)d_out;

    // host-side attribute set (idempotent; capture-safe — R12 precedent)
    cudaFuncSetAttribute(gemm_mma<0>, cudaFuncAttributeMaxDynamicSharedMemorySize, GSMEM);
    cudaFuncSetAttribute(gemm_mma<1>, cudaFuncAttributeMaxDynamicSharedMemorySize, GSMEM);

    fused_hs_kernel<<<BB * TT, 256>>>(hs, b_w, a_w, dt_bias, A_log);            // 0
    convert_w_big<<<NBIG, 256>>>(qkv_w, z_w);                                   // 1
    convert_w_out<<<HIDN, 256>>>(out_w);                                        // 2
    // merged qkv+z projection -> g_mixed, g_z   (profiled slot)
    gemm_mma<0><<<dim3(NBIG / 128, (BB * TT) / 128), 256, GSMEM>>>(nullptr);    // 3
    conv_kernel<<<dim3(CDIM / 256, TT / 128, BB), 256>>>(conv_w);               // 4
    scan_kernel<<<dim3(4, NH, BB), 256>>>();                                    // 5
    normgate_kernel<<<BB * TT, 256>>>(norm_w);                                  // 6
    gemm_mma<1><<<dim3(HIDN / 128, (BB * TT) / 128), 256, GSMEM>>>(out);        // 7
}

// round 16
// speedup vs baseline: 1.1678x; 1.0061x over previous
#include <cuda_runtime.h>
#include <cuda_bf16.h>
#include <math.h>
#include <stdint.h>

// Problem constants
#define BB   4
#define TT   1024
#define HIDN 1024
#define NH   8
#define CDIM 3072   // 2*H*DK + H*DV
#define NBIG 4096   // merged N: qkv (3072) + z (1024)
#define K3   3072   // tripled K for split-bf16 GEMM

// GEMM pipeline geometry (3-stage ring, R11 layout per stage)
#define GBUF  20480                 // one stage: A(128x80B) + B(128x80B)
#define GSMEM (3 * GBUF)            // 61440 bytes dynamic

// ---------------------------------------------------------------------------
// Scratch (device globals; allocation is forbidden)
// ---------------------------------------------------------------------------
__device__ float g_mixed[(size_t)BB * TT * CDIM];
__device__ float g_qkvc [(size_t)BB * TT * CDIM];
__device__ float g_z    [(size_t)BB * TT * HIDN];
__device__ float g_opre [(size_t)BB * TT * HIDN];
__device__ float g_alpha[(size_t)BB * NH * TT];
__device__ float g_beta [(size_t)BB * NH * TT];

// split-bf16 operands (K-tripled): A = [hi, lo, hi], B = [hi, hi, lo]
__device__ __nv_bfloat16 g_A3hs [(size_t)BB * TT * K3];   // hidden_states
__device__ __nv_bfloat16 g_A3og [(size_t)BB * TT * K3];   // gated/normed output
__device__ __nv_bfloat16 g_B3big[(size_t)NBIG * K3];      // [qkv_w ; z_w]
__device__ __nv_bfloat16 g_B3out[(size_t)HIDN * K3];      // out_w

// ---------------------------------------------------------------------------
// Base-ISA helpers (sm_80+ only: harness PTX targets compute_103, no 'a').
// ---------------------------------------------------------------------------
__device__ __forceinline__ uint32_t smem_u32(const void* p) {
    return (uint32_t)__cvta_generic_to_shared(p);
}
__device__ __forceinline__ void cp_async16(uint32_t dst, const void* src) {
    asm volatile("cp.async.cg.shared.global [%0], [%1], 16;" :: "r"(dst), "l"(src) : "memory");
}
#define CP_COMMIT() asm volatile("cp.async.commit_group;" ::: "memory")
#define CP_WAIT1()  asm volatile("cp.async.wait_group 1;" ::: "memory")

__device__ __forceinline__ void ldsm_x4(uint32_t* r, uint32_t addr) {
    asm volatile("ldmatrix.sync.aligned.m8n8.x4.shared.b16 {%0,%1,%2,%3}, [%4];"
                 : "=r"(r[0]), "=r"(r[1]), "=r"(r[2]), "=r"(r[3]) : "r"(addr));
}
__device__ __forceinline__ void mma16816(float* c, const uint32_t* a, uint32_t b0, uint32_t b1) {
    asm volatile("mma.sync.aligned.m16n8k16.row.col.f32.bf16.bf16.f32 "
                 "{%0,%1,%2,%3}, {%4,%5,%6,%7}, {%8,%9}, {%0,%1,%2,%3};"
                 : "+f"(c[0]), "+f"(c[1]), "+f"(c[2]), "+f"(c[3])
                 : "r"(a[0]), "r"(a[1]), "r"(a[2]), "r"(a[3]), "r"(b0), "r"(b1));
}

// hi/lo split helpers
__device__ __forceinline__ void split_bf16(float x, __nv_bfloat16& h, __nv_bfloat16& l) {
    h = __float2bfloat16_rn(x);
    l = __float2bfloat16_rn(x - __bfloat162float(h));
}
__device__ __forceinline__ void st_bf16x4(__nv_bfloat16* p, __nv_bfloat16 a, __nv_bfloat16 b,
                                          __nv_bfloat16 c, __nv_bfloat16 d) {
    __nv_bfloat162 v0; v0.x = a; v0.y = b;
    __nv_bfloat162 v1; v1.x = c; v1.y = d;
    *(__nv_bfloat162*)(p)     = v0;
    *(__nv_bfloat162*)(p + 2) = v1;
}

// ---------------------------------------------------------------------------
// MERGED PREP: (a) weight row convert for B3big (rows 0..4095: qkv_w then z_w),
// (b) hs row convert -> A3hs, (c) b/a projections -> alpha/beta.
// Grid 4096 blocks x 256 threads; the three parts are independent and their
// bodies are verbatim from the R15-proven kernels.
// ---------------------------------------------------------------------------
__global__ void __launch_bounds__(256) prep_kernel(const float* __restrict__ hs,
                                                   const float* __restrict__ qkv_w,
                                                   const float* __restrict__ z_w,
                                                   const float* __restrict__ b_w,
                                                   const float* __restrict__ a_w,
                                                   const float* __restrict__ dt_bias,
                                                   const float* __restrict__ A_log) {
    __shared__ float sh[1024];
    const int bt  = blockIdx.x;          // doubles as hs row AND weight row
    const int tid = threadIdx.x;
    const int c   = tid * 4;

    // ---- (a) weight convert: row bt of [qkv_w ; z_w] -> g_B3big [hi,hi,lo]
    {
        const float* src = (bt < 3072) ? (qkv_w + (size_t)bt * 1024)
                                       : (z_w + (size_t)(bt - 3072) * 1024);
        float4 xw = *(const float4*)(src + c);
        __nv_bfloat16 h0, h1, h2, h3, l0, l1, l2, l3;
        split_bf16(xw.x, h0, l0); split_bf16(xw.y, h1, l1);
        split_bf16(xw.z, h2, l2); split_bf16(xw.w, h3, l3);
        __nv_bfloat16* dst = g_B3big + (size_t)bt * K3 + c;
        st_bf16x4(dst,        h0, h1, h2, h3);
        st_bf16x4(dst + 1024, h0, h1, h2, h3);
        st_bf16x4(dst + 2048, l0, l1, l2, l3);
    }

    // ---- (b) hs convert -> g_A3hs [hi,lo,hi]  (also stage row for (c))
    float4 x = *(const float4*)(hs + (size_t)bt * 1024 + c);
    *(float4*)&sh[c] = x;
    {
        __nv_bfloat16 h0, h1, h2, h3, l0, l1, l2, l3;
        split_bf16(x.x, h0, l0); split_bf16(x.y, h1, l1);
        split_bf16(x.z, h2, l2); split_bf16(x.w, h3, l3);
        __nv_bfloat16* dst = g_A3hs + (size_t)bt * K3 + c;
        st_bf16x4(dst,        h0, h1, h2, h3);
        st_bf16x4(dst + 1024, l0, l1, l2, l3);
        st_bf16x4(dst + 2048, h0, h1, h2, h3);
    }
    __syncthreads();

    // ---- (c) b/a projections -> alpha/beta (warp per head)
    const int h = tid >> 5, lane = tid & 31;
    const float* bw = b_w + h * 1024;
    const float* aw = a_w + h * 1024;
    float sb = 0.f, sa = 0.f;
#pragma unroll
    for (int i = 0; i < 8; i++) {
        int idx = lane * 4 + i * 128;
        float4 xx = *(float4*)&sh[idx];
        float4 wb = *(const float4*)(bw + idx);
        float4 wa = *(const float4*)(aw + idx);
        sb += xx.x * wb.x + xx.y * wb.y + xx.z * wb.z + xx.w * wb.w;
        sa += xx.x * wa.x + xx.y * wa.y + xx.z * wa.z + xx.w * wa.w;
    }
#pragma unroll
    for (int m = 16; m; m >>= 1) {
        sb += __shfl_xor_sync(0xffffffffu, sb, m);
        sa += __shfl_xor_sync(0xffffffffu, sa, m);
    }
    if (lane == 0) {
        float beta = 1.f / (1.f + expf(-sb));
        float xg  = sa + dt_bias[h];
        float sp = (xg > 20.f) ? xg : log1pf(expf(xg));
        float g  = -expf(A_log[h]) * sp;
        int b = bt >> 10, t = bt & 1023;
        g_alpha[((b * NH + h) << 10) + t] = expf(g);
        g_beta [((b * NH + h) << 10) + t] = beta;
    }
}

// ---------------------------------------------------------------------------
// out_w conversion (independent; runs after the scan, before gemm<1>)
// ---------------------------------------------------------------------------
__global__ void __launch_bounds__(256) convert_w_out(const float* __restrict__ src) {
    const int row = blockIdx.x;
    const int c   = threadIdx.x * 4;
    float4 x = *(const float4*)(src + (size_t)row * 1024 + c);
    __nv_bfloat16 h0, h1, h2, h3, l0, l1, l2, l3;
    split_bf16(x.x, h0, l0); split_bf16(x.y, h1, l1);
    split_bf16(x.z, h2, l2); split_bf16(x.w, h3, l3);
    __nv_bfloat16* dst = g_B3out + (size_t)row * K3 + c;
    st_bf16x4(dst,        h0, h1, h2, h3);
    st_bf16x4(dst + 1024, h0, h1, h2, h3);
    st_bf16x4(dst + 2048, l0, l1, l2, l3);
}

// ---------------------------------------------------------------------------
// HMMA GEMM (NT): R15-exact (3-stage ring, BK=32, 80B rows — measured best).
//   WHICH 0: A3hs x B3big (N=4096) -> cols<3072 g_mixed, else g_z
//   WHICH 1: A3og x B3out (N=1024) -> Cext
// ---------------------------------------------------------------------------
template <int WHICH>
__global__ void __launch_bounds__(256) gemm_mma(float* __restrict__ Cext) {
    const __nv_bfloat16* A = WHICH ? g_A3og : g_A3hs;
    const __nv_bfloat16* B = WHICH ? g_B3out : g_B3big;

    extern __shared__ __align__(16) char smem[];
    const uint32_t sB = smem_u32(smem);

    const int tid  = threadIdx.x;
    const int bn   = blockIdx.x * 128;
    const int bm   = blockIdx.y * 128;
    const int warp = tid >> 5, lane = tid & 31;
    const int wm   = (warp >> 2) * 64;
    const int wn   = (warp & 3) * 32;

    float acc[4][4][4];
#pragma unroll
    for (int im = 0; im < 4; im++)
#pragma unroll
        for (int in = 0; in < 4; in++)
#pragma unroll
            for (int r = 0; r < 4; r++) acc[im][in][r] = 0.f;

    const int lr = tid >> 2;
    const int kc = tid & 3;
    const __nv_bfloat16* Ag0 = A + (size_t)(bm + lr)      * K3 + kc * 8;
    const __nv_bfloat16* Ag1 = A + (size_t)(bm + lr + 64) * K3 + kc * 8;
    const __nv_bfloat16* Bg0 = B + (size_t)(bn + lr)      * K3 + kc * 8;
    const __nv_bfloat16* Bg1 = B + (size_t)(bn + lr + 64) * K3 + kc * 8;

    const uint32_t dA0 = lr * 80 + kc * 16;
    const uint32_t dA1 = (lr + 64) * 80 + kc * 16;

#define LOAD_STAGE(base, k0)                                  \
    do {                                                      \
        cp_async16((base) + dA0,         Ag0 + (k0));         \
        cp_async16((base) + dA1,         Ag1 + (k0));         \
        cp_async16((base) + 10240 + dA0, Bg0 + (k0));         \
        cp_async16((base) + 10240 + dA1, Bg1 + (k0));         \
        CP_COMMIT();                                          \
    } while (0)

    LOAD_STAGE(sB, 0);
    LOAD_STAGE(sB + GBUF, 32);

    const uint32_t aFo = (wm + (lane & 15)) * 80 + (lane >> 4) * 16;
    const uint32_t bFo = 10240 + (wn + (lane & 15)) * 80 + (lane >> 4) * 16;

    int cur = 0;
    const int NT = K3 / 32;   // 96
    for (int s = 0; s < NT; s++) {
        CP_WAIT1();
        __syncthreads();

        if (s + 2 < NT) {
            int nxt = cur + 2; if (nxt >= 3) nxt -= 3;
            LOAD_STAGE(sB + nxt * GBUF, (s + 2) * 32);
        }

        const uint32_t base = sB + cur * GBUF;
        const uint32_t aF = base + aFo;
        const uint32_t bF = base + bFo;

#pragma unroll
        for (int ks = 0; ks < 32; ks += 16) {
            uint32_t bfr[2][4];
            ldsm_x4(bfr[0], bF + ks * 2);
            ldsm_x4(bfr[1], bF + 16 * 80 + ks * 2);
#pragma unroll
            for (int im = 0; im < 4; im++) {
                uint32_t afr[4];
                ldsm_x4(afr, aF + im * (16 * 80) + ks * 2);
                mma16816(acc[im][0], afr, bfr[0][0], bfr[0][2]);
                mma16816(acc[im][1], afr, bfr[0][1], bfr[0][3]);
                mma16816(acc[im][2], afr, bfr[1][0], bfr[1][2]);
                mma16816(acc[im][3], afr, bfr[1][1], bfr[1][3]);
            }
        }

        cur = (cur == 2) ? 0 : cur + 1;
    }
#undef LOAD_STAGE

    float* Cb; int stride, cb;
    if (WHICH == 1)     { Cb = Cext;    stride = 1024; cb = bn; }
    else if (bn < 3072) { Cb = g_mixed; stride = 3072; cb = bn; }
    else                { Cb = g_z;     stride = 1024; cb = bn - 3072; }

    const int er = lane >> 2;
    const int ec = (lane & 3) * 2;
#pragma unroll
    for (int im = 0; im < 4; im++) {
#pragma unroll
        for (int in = 0; in < 4; in++) {
            const int r0  = bm + wm + im * 16 + er;
            const int col = cb + wn + in * 8 + ec;
            *(float2*)&Cb[(size_t)r0 * stride + col]       = make_float2(acc[im][in][0], acc[im][in][1]);
            *(float2*)&Cb[(size_t)(r0 + 8) * stride + col] = make_float2(acc[im][in][2], acc[im][in][3]);
        }
    }
}

// ---------------------------------------------------------------------------
// Causal depthwise conv1d (K=4)  (R15-exact)
// ---------------------------------------------------------------------------
__global__ void __launch_bounds__(256) conv_kernel(const float* __restrict__ conv_w) {
    const int c  = blockIdx.x * 256 + threadIdx.x;
    const int t0 = blockIdx.y * 128;
    const int b  = blockIdx.z;
    float4 w4 = *(const float4*)(conv_w + c * 4);
    const float* xin  = g_mixed + (size_t)b * TT * CDIM + c;
    float*       yout = g_qkvc  + (size_t)b * TT * CDIM + c;
    float x0 = (t0 >= 3) ? xin[(size_t)(t0 - 3) * CDIM] : 0.f;
    float x1 = (t0 >= 2) ? xin[(size_t)(t0 - 2) * CDIM] : 0.f;
    float x2 = (t0 >= 1) ? xin[(size_t)(t0 - 1) * CDIM] : 0.f;
#pragma unroll 4
    for (int t = t0; t < t0 + 128; t++) {
        float x3 = xin[(size_t)t * CDIM];
        yout[(size_t)t * CDIM] = w4.x * x0 + w4.y * x1 + w4.z * x2 + w4.w * x3;
        x0 = x1; x1 = x2; x2 = x3;
    }
}

// ---------------------------------------------------------------------------
// Gated delta-rule scan (R15-exact v2 body; now in the profiled launch slot).
// grid = (4 dv-chunks, H, B) = 128 CTAs, 256 threads.
// ---------------------------------------------------------------------------
__global__ void __launch_bounds__(256) scan_kernel() {
    __shared__ float sk[16][160];
    __shared__ float sq[16][160];
    __shared__ float sv[16][32];
    __shared__ float so[16][32];
    __shared__ float sal[16];
    __shared__ float sbe[16];

    const int tid   = threadIdx.x;
    const int chunk = blockIdx.x;
    const int h     = blockIdx.y;
    const int b     = blockIdx.z;

    const int lane  = tid & 31;
    const int w     = tid >> 5;
    const int split = lane & 7;
    const int col   = w * 4 + (lane >> 3);
    const int kbp   = split * 20;

    const float* qbase = g_qkvc + (size_t)b * TT * CDIM + h * 128;
    const float* abase = g_alpha + ((size_t)(b * NH + h) << 10);
    const float* bbase = g_beta  + ((size_t)(b * NH + h) << 10);

    float S[16];
#pragma unroll
    for (int j = 0; j < 16; j++) S[j] = 0.f;

    const int ltt  = tid >> 4;
    const int lseg = tid & 15;
    const int cc0  = lseg * 8;
    const int cc1  = cc0 + 4;
    const int d0   = cc0 + ((cc0 >> 4) << 2);
    const int d1   = cc1 + ((cc1 >> 4) << 2);

    float4 pq0, pq1, pk0, pk1, pv;
    float pal = 0.f, pbe = 0.f;
    {
        const float* row = qbase + (size_t)ltt * CDIM;
        pq0 = *(const float4*)(row + cc0);
        pq1 = *(const float4*)(row + cc1);
        pk0 = *(const float4*)(row + 1024 + cc0);
        pk1 = *(const float4*)(row + 1024 + cc1);
        if (lseg < 8) pv = *(const float4*)(row + 2048 + chunk * 32 + lseg * 4);
        if (tid < 16) { pal = abase[tid]; pbe = bbase[tid]; }
    }

    for (int t0 = 0; t0 < TT; t0 += 16) {
        __syncthreads();
        if (t0 > 0) {
            for (int idx = tid; idx < 512; idx += 256) {
                int tt = idx >> 5, dd = idx & 31;
                g_opre[(((size_t)(b * TT + (t0 - 16) + tt)) * NH + h) * 128 + chunk * 32 + dd] = so[tt][dd];
            }
        }
        *(float4*)&sq[ltt][d0] = pq0;
        *(float4*)&sq[ltt][d1] = pq1;
        *(float4*)&sk[ltt][d0] = pk0;
        *(float4*)&sk[ltt][d1] = pk1;
        if (lseg < 8) *(float4*)&sv[ltt][lseg * 4] = pv;
        if (tid < 16) { sal[tid] = pal; sbe[tid] = pbe; }
        __syncthreads();

        if (t0 + 16 < TT) {
            const float* row = qbase + (size_t)(t0 + 16 + ltt) * CDIM;
            pq0 = *(const float4*)(row + cc0);
            pq1 = *(const float4*)(row + cc1);
            pk0 = *(const float4*)(row + 1024 + cc0);
            pk1 = *(const float4*)(row + 1024 + cc1);
            if (lseg < 8) pv = *(const float4*)(row + 2048 + chunk * 32 + lseg * 4);
            if (tid < 16) { pal = abase[t0 + 16 + tid]; pbe = bbase[t0 + 16 + tid]; }
        }

#pragma unroll 2
        for (int tt = 0; tt < 16; tt++) {
            const float alpha = sal[tt];
            const float beta  = sbe[tt];

            float kr[16];
#pragma unroll
            for (int uu = 0; uu < 4; uu++)
                *(float4*)&kr[uu * 4] = *(float4*)&sk[tt][kbp + uu * 4];

            float kva = 0.f, kvb = 0.f, kvc = 0.f, kvd = 0.f;
#pragma unroll
            for (int j = 0; j < 16; j += 4) {
                S[j]     *= alpha; kva = fmaf(kr[j],     S[j],     kva);
                S[j + 1] *= alpha; kvb = fmaf(kr[j + 1], S[j + 1], kvb);
                S[j + 2] *= alpha; kvc = fmaf(kr[j + 2], S[j + 2], kvc);
                S[j + 3] *= alpha; kvd = fmaf(kr[j + 3], S[j + 3], kvd);
            }
            float kv = (kva + kvb) + (kvc + kvd);
            kv += __shfl_xor_sync(0xffffffffu, kv, 1);
            kv += __shfl_xor_sync(0xffffffffu, kv, 2);
            kv += __shfl_xor_sync(0xffffffffu, kv, 4);

            const float wv = (sv[tt][col] - kv) * beta;

            float qr[16];
#pragma unroll
            for (int uu = 0; uu < 4; uu++)
                *(float4*)&qr[uu * 4] = *(float4*)&sq[tt][kbp + uu * 4];

            float oa = 0.f, ob = 0.f, oc = 0.f, od = 0.f;
#pragma unroll
            for (int j = 0; j < 16; j += 4) {
                S[j]     = fmaf(kr[j],     wv, S[j]);     oa = fmaf(qr[j],     S[j],     oa);
                S[j + 1] = fmaf(kr[j + 1], wv, S[j + 1]); ob = fmaf(qr[j + 1], S[j + 1], ob);
                S[j + 2] = fmaf(kr[j + 2], wv, S[j + 2]); oc = fmaf(qr[j + 2], S[j + 2], oc);
                S[j + 3] = fmaf(kr[j + 3], wv, S[j + 3]); od = fmaf(qr[j + 3], S[j + 3], od);
            }
            float o = (oa + ob) + (oc + od);
            o += __shfl_xor_sync(0xffffffffu, o, 1);
            o += __shfl_xor_sync(0xffffffffu, o, 2);
            o += __shfl_xor_sync(0xffffffffu, o, 4);
            if (split == 0) so[tt][col] = o;
        }
    }

    __syncthreads();
    for (int idx = tid; idx < 512; idx += 256) {
        int tt = idx >> 5, dd = idx & 31;
        g_opre[(((size_t)(b * TT + (TT - 16) + tt)) * NH + h) * 128 + chunk * 32 + dd] = so[tt][dd];
    }
}

// ---------------------------------------------------------------------------
// Gated RMSNorm fused with split-bf16 A-operand emission (R15-exact)
// ---------------------------------------------------------------------------
__global__ void __launch_bounds__(256) normgate_kernel(const float* __restrict__ norm_w) {
    const int bt   = blockIdx.x;
    const int h    = threadIdx.x >> 5;
    const int lane = threadIdx.x & 31;

    const size_t obase = ((size_t)bt * NH + h) * 128 + lane * 4;
    float4 o4 = *(const float4*)(g_opre + obase);
    float ss = o4.x * o4.x + o4.y * o4.y + o4.z * o4.z + o4.w * o4.w;
#pragma unroll
    for (int m = 16; m; m >>= 1) ss += __shfl_xor_sync(0xffffffffu, ss, m);
    const float scale = rsqrtf(ss * (1.f / 128.f) + 1e-6f);

    const size_t zbase = (size_t)bt * 1024 + h * 128 + lane * 4;
    float4 z4 = *(const float4*)(g_z + zbase);
    float4 nw = *(const float4*)(norm_w + lane * 4);
    float rx = o4.x * scale * nw.x * (z4.x / (1.f + expf(-z4.x)));
    float ry = o4.y * scale * nw.y * (z4.y / (1.f + expf(-z4.y)));
    float rz = o4.z * scale * nw.z * (z4.z / (1.f + expf(-z4.z)));
    float rw = o4.w * scale * nw.w * (z4.w / (1.f + expf(-z4.w)));

    __nv_bfloat16 h0, h1, h2, h3, l0, l1, l2, l3;
    split_bf16(rx, h0, l0); split_bf16(ry, h1, l1);
    split_bf16(rz, h2, l2); split_bf16(rw, h3, l3);
    __nv_bfloat16* dst = g_A3og + (size_t)bt * K3 + h * 128 + lane * 4;
    st_bf16x4(dst,        h0, h1, h2, h3);
    st_bf16x4(dst + 1024, l0, l1, l2, l3);
    st_bf16x4(dst + 2048, h0, h1, h2, h3);
}

// ---------------------------------------------------------------------------
// kernel_launch  (scan_kernel now at launch index 3 = the profiled slot)
// ---------------------------------------------------------------------------
extern "C" void kernel_launch(void* const* d_in, const int* in_sizes, int n_in,
                              void* d_out, int out_size) {
    const float* hs      = (const float*)d_in[0];
    const float* qkv_w   = (const float*)d_in[1];
    const float* z_w     = (const float*)d_in[2];
    const float* b_w     = (const float*)d_in[3];
    const float* a_w     = (const float*)d_in[4];
    const float* conv_w  = (const float*)d_in[5];
    const float* dt_bias = (const float*)d_in[6];
    const float* A_log   = (const float*)d_in[7];
    const float* norm_w  = (const float*)d_in[8];
    const float* out_w   = (const float*)d_in[9];
    float* out = (float*)d_out;

    // host-side attribute set (idempotent; capture-safe — R12/R15 precedent)
    cudaFuncSetAttribute(gemm_mma<0>, cudaFuncAttributeMaxDynamicSharedMemorySize, GSMEM);
    cudaFuncSetAttribute(gemm_mma<1>, cudaFuncAttributeMaxDynamicSharedMemorySize, GSMEM);

    prep_kernel<<<NBIG, 256>>>(hs, qkv_w, z_w, b_w, a_w, dt_bias, A_log);       // 0
    gemm_mma<0><<<dim3(NBIG / 128, (BB * TT) / 128), 256, GSMEM>>>(nullptr);    // 1
    conv_kernel<<<dim3(CDIM / 256, TT / 128, BB), 256>>>(conv_w);               // 2
    scan_kernel<<<dim3(4, NH, BB), 256>>>();                                    // 3  (profiled)
    convert_w_out<<<HIDN, 256>>>(out_w);                                        // 4
    normgate_kernel<<<BB * TT, 256>>>(norm_w);                                  // 5
    gemm_mma<1><<<dim3(HIDN / 128, (BB * TT) / 128), 256, GSMEM>>>(out);        // 6
}